// round 1
// baseline (speedup 1.0000x reference)
#include <cuda_runtime.h>

// PLRNN step:
//   H  = relu(Z @ W1^T + h1)              Z:[8192,1024] W1:[4096,1024] -> H:[8192,4096]
//   out = A*Z + H @ W2^T + h2 + S @ C^T   W2:[1024,4096] S:[8192,64] C:[1024,64]
//
// Both GEMMs are "NT" (K contiguous in both operands) -> float4 loads everywhere.
// Two kernels, H staged in a __device__ scratch (no allocation).

#define BM 128
#define BN 128
#define BK 16
#define TM 8
#define TN 8
#define NTHREADS 256

static __device__ float g_H[8192ull * 4096ull];   // 128 MiB scratch, .bss

// Each thread loads 2 float4 of a 128x16 (rows x K) tile.
__device__ __forceinline__ void load_tile_regs(const float* __restrict__ g,
                                               int ld, int row0, int k0,
                                               int tid, float4 v[2]) {
#pragma unroll
    for (int it = 0; it < 2; it++) {
        int idx = tid + it * NTHREADS;   // 0..511
        int row = idx >> 2;              // 0..127
        int c4  = idx & 3;               // 0..3 (float4 along K)
        v[it] = *reinterpret_cast<const float4*>(
            g + (size_t)(row0 + row) * ld + k0 + c4 * 4);
    }
}

// Store transposed into smem: sm[k][row], sm is BK x 128.
__device__ __forceinline__ void store_tile_smem(float* __restrict__ sm,
                                                int tid, const float4 v[2]) {
#pragma unroll
    for (int it = 0; it < 2; it++) {
        int idx = tid + it * NTHREADS;
        int row = idx >> 2;
        int c4  = idx & 3;
        sm[(c4 * 4 + 0) * BM + row] = v[it].x;
        sm[(c4 * 4 + 1) * BM + row] = v[it].y;
        sm[(c4 * 4 + 2) * BM + row] = v[it].z;
        sm[(c4 * 4 + 3) * BM + row] = v[it].w;
    }
}

__device__ __forceinline__ void compute_tile(const float* __restrict__ As,
                                             const float* __restrict__ Bs,
                                             int mt, int nt,
                                             float (&acc)[TM][TN]) {
#pragma unroll
    for (int k = 0; k < BK; k++) {
        float a[TM], b[TN];
        *reinterpret_cast<float4*>(&a[0]) =
            *reinterpret_cast<const float4*>(As + k * BM + mt * TM);
        *reinterpret_cast<float4*>(&a[4]) =
            *reinterpret_cast<const float4*>(As + k * BM + mt * TM + 4);
        *reinterpret_cast<float4*>(&b[0]) =
            *reinterpret_cast<const float4*>(Bs + k * BN + nt * TN);
        *reinterpret_cast<float4*>(&b[4]) =
            *reinterpret_cast<const float4*>(Bs + k * BN + nt * TN + 4);
#pragma unroll
        for (int i = 0; i < TM; i++)
#pragma unroll
            for (int j = 0; j < TN; j++)
                acc[i][j] = fmaf(a[i], b[j], acc[i][j]);
    }
}

// ---------------- Kernel 1: H = relu(Z @ W1^T + h1) ----------------
// M=8192, N=4096, K=1024
__global__ void __launch_bounds__(NTHREADS, 2)
k_gemm1(const float* __restrict__ Z, const float* __restrict__ W1,
        const float* __restrict__ h1) {
    const int K = 1024, N = 4096;
    __shared__ float As[2][BK * BM];
    __shared__ float Bs[2][BK * BN];

    const int tid = threadIdx.x;
    const int bm = blockIdx.y * BM;
    const int bn = blockIdx.x * BN;
    const int mt = tid >> 4;   // 0..15
    const int nt = tid & 15;   // 0..15

    float acc[TM][TN];
#pragma unroll
    for (int i = 0; i < TM; i++)
#pragma unroll
        for (int j = 0; j < TN; j++) acc[i][j] = 0.f;

    float4 av[2], bv[2];
    load_tile_regs(Z,  K, bm, 0, tid, av);
    load_tile_regs(W1, K, bn, 0, tid, bv);
    store_tile_smem(As[0], tid, av);
    store_tile_smem(Bs[0], tid, bv);
    __syncthreads();

    const int ntiles = K / BK;
    for (int kt = 0; kt < ntiles; kt++) {
        int buf = kt & 1;
        if (kt + 1 < ntiles) {
            load_tile_regs(Z,  K, bm, (kt + 1) * BK, tid, av);
            load_tile_regs(W1, K, bn, (kt + 1) * BK, tid, bv);
        }
        compute_tile(As[buf], Bs[buf], mt, nt, acc);
        if (kt + 1 < ntiles) {
            store_tile_smem(As[buf ^ 1], tid, av);
            store_tile_smem(Bs[buf ^ 1], tid, bv);
        }
        __syncthreads();
    }

    // Epilogue: + h1, relu, store to g_H
#pragma unroll
    for (int i = 0; i < TM; i++) {
        int row = bm + mt * TM + i;
        float* hrow = g_H + (size_t)row * N + bn + nt * TN;
#pragma unroll
        for (int j = 0; j < TN; j += 4) {
            int col = bn + nt * TN + j;
            float4 o;
            o.x = fmaxf(acc[i][j + 0] + h1[col + 0], 0.f);
            o.y = fmaxf(acc[i][j + 1] + h1[col + 1], 0.f);
            o.z = fmaxf(acc[i][j + 2] + h1[col + 2], 0.f);
            o.w = fmaxf(acc[i][j + 3] + h1[col + 3], 0.f);
            *reinterpret_cast<float4*>(hrow + j) = o;
        }
    }
}

// ---------------- Kernel 2: out = A*Z + H @ W2^T + h2 + S @ C^T ----------------
// M=8192, N=1024, K=4096 (+ K2=64 for S@C^T)
__global__ void __launch_bounds__(NTHREADS, 2)
k_gemm2(const float* __restrict__ W2, const float* __restrict__ S,
        const float* __restrict__ C,  const float* __restrict__ Avec,
        const float* __restrict__ Z,  const float* __restrict__ h2,
        float* __restrict__ out) {
    const int K = 4096, N = 1024, KS = 64;
    __shared__ float As[2][BK * BM];
    __shared__ float Bs[2][BK * BN];

    const int tid = threadIdx.x;
    const int bm = blockIdx.y * BM;
    const int bn = blockIdx.x * BN;
    const int mt = tid >> 4;
    const int nt = tid & 15;

    float acc[TM][TN];
#pragma unroll
    for (int i = 0; i < TM; i++)
#pragma unroll
        for (int j = 0; j < TN; j++) acc[i][j] = 0.f;

    float4 av[2], bv[2];
    load_tile_regs(g_H, K, bm, 0, tid, av);
    load_tile_regs(W2,  K, bn, 0, tid, bv);
    store_tile_smem(As[0], tid, av);
    store_tile_smem(Bs[0], tid, bv);
    __syncthreads();

    const int ntiles = K / BK;
    for (int kt = 0; kt < ntiles; kt++) {
        int buf = kt & 1;
        if (kt + 1 < ntiles) {
            load_tile_regs(g_H, K, bm, (kt + 1) * BK, tid, av);
            load_tile_regs(W2,  K, bn, (kt + 1) * BK, tid, bv);
        }
        compute_tile(As[buf], Bs[buf], mt, nt, acc);
        if (kt + 1 < ntiles) {
            store_tile_smem(As[buf ^ 1], tid, av);
            store_tile_smem(Bs[buf ^ 1], tid, bv);
        }
        __syncthreads();
    }
    // (loop above ends with all compute on the last buffer done + synced)

    // Phase 2: accumulate S @ C^T  (K=64 -> 4 tiles, no double-buffer needed)
    for (int kt = 0; kt < KS / BK; kt++) {
        load_tile_regs(S, KS, bm, kt * BK, tid, av);
        load_tile_regs(C, KS, bn, kt * BK, tid, bv);
        store_tile_smem(As[0], tid, av);
        store_tile_smem(Bs[0], tid, bv);
        __syncthreads();
        compute_tile(As[0], Bs[0], mt, nt, acc);
        __syncthreads();
    }

    // Epilogue: + A*z + h2
#pragma unroll
    for (int i = 0; i < TM; i++) {
        int row = bm + mt * TM + i;
        const float* zrow = Z + (size_t)row * N + bn + nt * TN;
        float* orow = out + (size_t)row * N + bn + nt * TN;
#pragma unroll
        for (int j = 0; j < TN; j += 4) {
            int col = bn + nt * TN + j;
            float4 zv = *reinterpret_cast<const float4*>(zrow + j);
            float4 o;
            o.x = acc[i][j + 0] + Avec[col + 0] * zv.x + h2[col + 0];
            o.y = acc[i][j + 1] + Avec[col + 1] * zv.y + h2[col + 1];
            o.z = acc[i][j + 2] + Avec[col + 2] * zv.z + h2[col + 2];
            o.w = acc[i][j + 3] + Avec[col + 3] * zv.w + h2[col + 3];
            *reinterpret_cast<float4*>(orow + j) = o;
        }
    }
}

extern "C" void kernel_launch(void* const* d_in, const int* in_sizes, int n_in,
                              void* d_out, int out_size) {
    // metadata order: z, s, A, W1, W2, h1, h2, C
    const float* z  = (const float*)d_in[0];
    const float* s  = (const float*)d_in[1];
    const float* A  = (const float*)d_in[2];
    const float* W1 = (const float*)d_in[3];
    const float* W2 = (const float*)d_in[4];
    const float* h1 = (const float*)d_in[5];
    const float* h2 = (const float*)d_in[6];
    const float* C  = (const float*)d_in[7];
    float* out = (float*)d_out;

    (void)in_sizes; (void)n_in; (void)out_size;

    dim3 block(NTHREADS);
    dim3 grid1(4096 / BN, 8192 / BM);   // 32 x 64
    dim3 grid2(1024 / BN, 8192 / BM);   //  8 x 64

    k_gemm1<<<grid1, block>>>(z, W1, h1);
    k_gemm2<<<grid2, block>>>(W2, s, C, A, z, h2, out);
}

// round 3
// speedup vs baseline: 3.2063x; 3.2063x over previous
#include <cuda_runtime.h>
#include <cstdint>

// PLRNN step via mma.sync tf32 (base-target ISA; tcgen05 rejected by harness ptxas).
//   prepass: round Z,W1,W2,S,C to tf32 (rna)
//   GEMM1:   H  = relu(Zr @ W1r^T + h1), H rounded to tf32     [8192,4096]
//   GEMM2:   out = A*z + H @ W2r^T + h2 + Sr @ Cr^T            [8192,1024]

#define NT 128
#define BM 128
#define BN 128
#define BK 16
#define DB 8192
#define DZv 1024
#define DHv 4096
#define DSv 64

static __device__ float g_H  [(size_t)DB * DHv];   // 128 MiB (tf32-rounded)
static __device__ float g_Zr [(size_t)DB * DZv];
static __device__ float g_W1r[(size_t)DHv * DZv];
static __device__ float g_W2r[(size_t)DZv * DHv];
static __device__ float g_Sr [(size_t)DB * DSv];
static __device__ float g_Cr [(size_t)DZv * DSv];

__device__ __forceinline__ float tf32_rn(float x) {
    uint32_t o;
    asm("cvt.rna.tf32.f32 %0, %1;" : "=r"(o) : "f"(x));
    return __uint_as_float(o);
}

__device__ __forceinline__ void mma_tf32(float& d0, float& d1, float& d2, float& d3,
                                         uint32_t a0, uint32_t a1, uint32_t a2, uint32_t a3,
                                         uint32_t b0, uint32_t b1) {
    asm volatile(
        "mma.sync.aligned.m16n8k8.row.col.f32.tf32.tf32.f32 "
        "{%0,%1,%2,%3}, {%4,%5,%6,%7}, {%8,%9}, {%0,%1,%2,%3};"
        : "+f"(d0), "+f"(d1), "+f"(d2), "+f"(d3)
        : "r"(a0), "r"(a1), "r"(a2), "r"(a3), "r"(b0), "r"(b1));
}

// smem: per buffer, A region 8448 B (16 slots x 528), B region 8448 B (32 slots x 264)
#define ABYTES 8448
#define BUFB   16896
#define SMEM_SZ (2 * BUFB)

// ---------------- prepass: tf32-round inputs ----------------
__global__ void k_prep(const float* __restrict__ z, const float* __restrict__ w1,
                       const float* __restrict__ w2, const float* __restrict__ s,
                       const float* __restrict__ c) {
    const float* src; float* dst; size_t n4;
    switch (blockIdx.y) {
        case 0:  src = z;  dst = g_Zr;  n4 = (size_t)DB * DZv / 4;  break;
        case 1:  src = w1; dst = g_W1r; n4 = (size_t)DHv * DZv / 4; break;
        case 2:  src = w2; dst = g_W2r; n4 = (size_t)DZv * DHv / 4; break;
        case 3:  src = s;  dst = g_Sr;  n4 = (size_t)DB * DSv / 4;  break;
        default: src = c;  dst = g_Cr;  n4 = (size_t)DZv * DSv / 4; break;
    }
    size_t stride = (size_t)gridDim.x * blockDim.x;
    for (size_t i = (size_t)blockIdx.x * blockDim.x + threadIdx.x; i < n4; i += stride) {
        float4 v = reinterpret_cast<const float4*>(src)[i];
        v.x = tf32_rn(v.x); v.y = tf32_rn(v.y);
        v.z = tf32_rn(v.z); v.w = tf32_rn(v.w);
        reinterpret_cast<float4*>(dst)[i] = v;
    }
}

// ---------------- mma.sync GEMM (MODE 0: GEMM1, MODE 1: GEMM2) ----------------
template <int MODE>
__global__ void __launch_bounds__(NT, 2)
k_mma(const float* __restrict__ bias, const float* __restrict__ Avec,
      const float* __restrict__ Zorig, float* __restrict__ out) {
    extern __shared__ char smc[];
    constexpr int KBIG = (MODE == 0) ? DZv : DHv;
    constexpr int NCB  = KBIG / BK;
    constexpr int NC   = (MODE == 0) ? NCB : NCB + DSv / BK;
    const float* gA = (MODE == 0) ? g_Zr  : g_H;
    const float* gB = (MODE == 0) ? g_W1r : g_W2r;

    const int tid  = threadIdx.x;
    const int lane = tid & 31;
    const int wid  = tid >> 5;
    const int wm = wid & 1, wn = wid >> 1;          // 2x2 warp grid, warp tile 64x64
    const int bm = blockIdx.y * BM, bn = blockIdx.x * BN;

    // ---- writer-side constants (each thread owns fixed (c4, row-residue)) ----
    const int c4  = tid & 3;            // which float4 along K (k = c4*4)
    const int ksw = c4 >> 1;            // kstep of this thread's elements
    const int hw  = c4 & 1;             // k-half within kstep
    const int rb  = tid >> 2;           // row residue 0..31 (rows rb + 32t)
    const int rtA = rb & 15;
    const int laneA0 = (rtA & 7) * 4;
    const int swzA = ((laneA0 >> 3) & 1) * 32;
    const int stA0 = ((rb >> 4) * 2 + ksw) * 528 + ((rtA >> 3) + 2 * hw) * 4;
    const int stB0 = ((rb >> 3) * 2 + ksw) * 264 + (rb & 7) * 32 + hw * 4;

    // ---- reader-side bases ----
    const int rdA0 = (wm * 8) * 528 + ((lane * 16) ^ (((lane >> 3) & 1) * 32));
    const int rdB0 = (wn * 16) * 264 + lane * 8;

    float acc[4][8][4];
#pragma unroll
    for (int i = 0; i < 4; i++)
#pragma unroll
        for (int j = 0; j < 8; j++)
#pragma unroll
            for (int k = 0; k < 4; k++) acc[i][j][k] = 0.f;

    const size_t rowA = (size_t)(bm + rb);
    const size_t rowB = (size_t)(bn + rb);

    float4 pa[4], pb[4];

    auto ldgc = [&](int cn) {
        if (MODE == 1 && cn >= NCB) {
            const float* a = g_Sr + rowA * DSv + (cn - NCB) * BK + c4 * 4;
            const float* b = g_Cr + rowB * DSv + (cn - NCB) * BK + c4 * 4;
#pragma unroll
            for (int t = 0; t < 4; t++) {
                pa[t] = *reinterpret_cast<const float4*>(a + t * 32 * DSv);
                pb[t] = *reinterpret_cast<const float4*>(b + t * 32 * DSv);
            }
        } else {
            const float* a = gA + rowA * KBIG + cn * BK + c4 * 4;
            const float* b = gB + rowB * KBIG + cn * BK + c4 * 4;
#pragma unroll
            for (int t = 0; t < 4; t++) {
                pa[t] = *reinterpret_cast<const float4*>(a + (size_t)t * 32 * KBIG);
                pb[t] = *reinterpret_cast<const float4*>(b + (size_t)t * 32 * KBIG);
            }
        }
    };

    auto stsc = [&](int buf) {
        char* A = smc + buf * BUFB;
        char* B = A + ABYTES;
#pragma unroll
        for (int t = 0; t < 4; t++) {
            const float* e = reinterpret_cast<const float*>(&pa[t]);
#pragma unroll
            for (int j = 0; j < 4; j++)
                *reinterpret_cast<float*>(
                    A + stA0 + t * 2112 + (((laneA0 + j) * 16) ^ swzA)) = e[j];
            const float* f = reinterpret_cast<const float*>(&pb[t]);
#pragma unroll
            for (int j = 0; j < 4; j++)
                *reinterpret_cast<float*>(B + stB0 + t * 2112 + j * 8) = f[j];
        }
    };

    auto comp = [&](int buf) {
        const char* A = smc + buf * BUFB;
        const char* B = A + ABYTES;
#pragma unroll
        for (int ks = 0; ks < 2; ks++) {
            uint32_t af[4][4];
            uint32_t bf[8][2];
#pragma unroll
            for (int mt = 0; mt < 4; mt++) {
                uint4 v = *reinterpret_cast<const uint4*>(A + rdA0 + ks * 528 + mt * 1056);
                af[mt][0] = v.x; af[mt][1] = v.y; af[mt][2] = v.z; af[mt][3] = v.w;
            }
#pragma unroll
            for (int nt = 0; nt < 8; nt++) {
                uint2 v = *reinterpret_cast<const uint2*>(B + rdB0 + ks * 264 + nt * 528);
                bf[nt][0] = v.x; bf[nt][1] = v.y;
            }
#pragma unroll
            for (int mt = 0; mt < 4; mt++)
#pragma unroll
                for (int nt = 0; nt < 8; nt++)
                    mma_tf32(acc[mt][nt][0], acc[mt][nt][1], acc[mt][nt][2], acc[mt][nt][3],
                             af[mt][0], af[mt][1], af[mt][2], af[mt][3],
                             bf[nt][0], bf[nt][1]);
        }
    };

    // ---- pipeline ----
    ldgc(0);
    stsc(0);
    __syncthreads();
    int buf = 0;
#pragma unroll 1
    for (int c = 0; c < NC; c++) {
        const bool nx = (c + 1 < NC);
        if (nx) ldgc(c + 1);
        comp(buf);
        if (nx) stsc(buf ^ 1);
        __syncthreads();
        buf ^= 1;
    }

    // ---- epilogue ----
    const int r0 = lane >> 2, cp = (lane & 3) * 2;
#pragma unroll
    for (int mt = 0; mt < 4; mt++) {
        const int row = bm + wm * 64 + mt * 16 + r0;
#pragma unroll
        for (int nt = 0; nt < 8; nt++) {
            const int col = bn + wn * 64 + nt * 8 + cp;
            const float b0 = __ldg(bias + col), b1 = __ldg(bias + col + 1);
            if (MODE == 0) {
                float2 v0 = make_float2(tf32_rn(fmaxf(acc[mt][nt][0] + b0, 0.f)),
                                        tf32_rn(fmaxf(acc[mt][nt][1] + b1, 0.f)));
                float2 v1 = make_float2(tf32_rn(fmaxf(acc[mt][nt][2] + b0, 0.f)),
                                        tf32_rn(fmaxf(acc[mt][nt][3] + b1, 0.f)));
                *reinterpret_cast<float2*>(g_H + (size_t)row * DHv + col) = v0;
                *reinterpret_cast<float2*>(g_H + (size_t)(row + 8) * DHv + col) = v1;
            } else {
                const float a0 = __ldg(Avec + col), a1 = __ldg(Avec + col + 1);
                float2 z0 = *reinterpret_cast<const float2*>(Zorig + (size_t)row * DZv + col);
                float2 z1 = *reinterpret_cast<const float2*>(Zorig + (size_t)(row + 8) * DZv + col);
                float2 v0 = make_float2(acc[mt][nt][0] + a0 * z0.x + b0,
                                        acc[mt][nt][1] + a1 * z0.y + b1);
                float2 v1 = make_float2(acc[mt][nt][2] + a0 * z1.x + b0,
                                        acc[mt][nt][3] + a1 * z1.y + b1);
                *reinterpret_cast<float2*>(out + (size_t)row * DZv + col) = v0;
                *reinterpret_cast<float2*>(out + (size_t)(row + 8) * DZv + col) = v1;
            }
        }
    }
}

extern "C" void kernel_launch(void* const* d_in, const int* in_sizes, int n_in,
                              void* d_out, int out_size) {
    // metadata order: z, s, A, W1, W2, h1, h2, C
    const float* z  = (const float*)d_in[0];
    const float* s  = (const float*)d_in[1];
    const float* A  = (const float*)d_in[2];
    const float* W1 = (const float*)d_in[3];
    const float* W2 = (const float*)d_in[4];
    const float* h1 = (const float*)d_in[5];
    const float* h2 = (const float*)d_in[6];
    const float* C  = (const float*)d_in[7];
    float* out = (float*)d_out;
    (void)in_sizes; (void)n_in; (void)out_size;

    k_prep<<<dim3(512, 5), 256>>>(z, W1, W2, s, C);
    k_mma<0><<<dim3(DHv / BN, DB / BM), NT, SMEM_SZ>>>(h1, nullptr, nullptr, nullptr);
    k_mma<1><<<dim3(DZv / BN, DB / BM), NT, SMEM_SZ>>>(h2, A, z, out);
}

// round 4
// speedup vs baseline: 8.4626x; 2.6394x over previous
#include <cuda_runtime.h>
#include <cuda_fp16.h>
#include <cstdint>

// PLRNN step via mma.sync fp16 (m16n8k16, fp32 accum) + cp.async 3-stage pipeline.
//   prepass: convert Z,W1,W2,S,C to fp16
//   GEMM1:   H  = relu(Zh @ W1h^T + h1) -> fp16              [8192,4096]
//   GEMM2:   out = A*z + Hh @ W2h^T + h2 + Sh @ Ch^T         [8192,1024] fp32

#define NT 128
#define BM 128
#define BN 128
#define BKH 32            // K halves per chunk (64 B per row)
#define DB 8192
#define DZv 1024
#define DHv 4096
#define DSv 64

static __device__ __align__(256) __half g_Hh [(size_t)DB * DHv];
static __device__ __align__(256) __half g_Zh [(size_t)DB * DZv];
static __device__ __align__(256) __half g_W1h[(size_t)DHv * DZv];
static __device__ __align__(256) __half g_W2h[(size_t)DZv * DHv];
static __device__ __align__(256) __half g_Sh [(size_t)DB * DSv];
static __device__ __align__(256) __half g_Ch [(size_t)DZv * DSv];

#define TILEB  8192               // 128 rows x 64 B
#define STAGEB (2 * TILEB)
#define SMEM_SZ (3 * STAGEB)      // 49152

__device__ __forceinline__ uint32_t smem_u32(const void* p) {
    uint32_t a;
    asm("{ .reg .u64 t; cvta.to.shared.u64 t, %1; cvt.u32.u64 %0, t; }" : "=r"(a) : "l"(p));
    return a;
}
__device__ __forceinline__ void cp16(uint32_t s, const void* g) {
    asm volatile("cp.async.cg.shared.global [%0], [%1], 16;" :: "r"(s), "l"(g));
}
#define CP_COMMIT() asm volatile("cp.async.commit_group;" ::: "memory")
#define CP_WAIT(n)  asm volatile("cp.async.wait_group %0;" :: "n"(n) : "memory")

__device__ __forceinline__ void ldsm4(uint32_t (&r)[4], uint32_t a) {
    asm volatile("ldmatrix.sync.aligned.m8n8.x4.shared.b16 {%0,%1,%2,%3}, [%4];"
        : "=r"(r[0]), "=r"(r[1]), "=r"(r[2]), "=r"(r[3]) : "r"(a));
}
__device__ __forceinline__ void mma16(float (&d)[4], const uint32_t (&a)[4],
                                      uint32_t b0, uint32_t b1) {
    asm volatile("mma.sync.aligned.m16n8k16.row.col.f32.f16.f16.f32 "
        "{%0,%1,%2,%3}, {%4,%5,%6,%7}, {%8,%9}, {%0,%1,%2,%3};"
        : "+f"(d[0]), "+f"(d[1]), "+f"(d[2]), "+f"(d[3])
        : "r"(a[0]), "r"(a[1]), "r"(a[2]), "r"(a[3]), "r"(b0), "r"(b1));
}

// ---------------- prepass: fp32 -> fp16 ----------------
__global__ void k_prep(const float* __restrict__ z, const float* __restrict__ w1,
                       const float* __restrict__ w2, const float* __restrict__ s,
                       const float* __restrict__ c) {
    const float* src; __half* dst; size_t n8;
    switch (blockIdx.y) {
        case 0:  src = z;  dst = g_Zh;  n8 = (size_t)DB * DZv / 8;  break;
        case 1:  src = w1; dst = g_W1h; n8 = (size_t)DHv * DZv / 8; break;
        case 2:  src = w2; dst = g_W2h; n8 = (size_t)DZv * DHv / 8; break;
        case 3:  src = s;  dst = g_Sh;  n8 = (size_t)DB * DSv / 8;  break;
        default: src = c;  dst = g_Ch;  n8 = (size_t)DZv * DSv / 8; break;
    }
    size_t stride = (size_t)gridDim.x * blockDim.x;
    for (size_t i = (size_t)blockIdx.x * blockDim.x + threadIdx.x; i < n8; i += stride) {
        float4 v0 = reinterpret_cast<const float4*>(src)[2 * i];
        float4 v1 = reinterpret_cast<const float4*>(src)[2 * i + 1];
        __half2 h0 = __floats2half2_rn(v0.x, v0.y);
        __half2 h1 = __floats2half2_rn(v0.z, v0.w);
        __half2 h2 = __floats2half2_rn(v1.x, v1.y);
        __half2 h3 = __floats2half2_rn(v1.z, v1.w);
        uint4 o;
        o.x = *reinterpret_cast<uint32_t*>(&h0);
        o.y = *reinterpret_cast<uint32_t*>(&h1);
        o.z = *reinterpret_cast<uint32_t*>(&h2);
        o.w = *reinterpret_cast<uint32_t*>(&h3);
        reinterpret_cast<uint4*>(dst)[i] = o;
    }
}

// ---------------- fp16 mma GEMM (MODE 0: GEMM1, MODE 1: GEMM2) ----------------
template <int MODE>
__global__ void __launch_bounds__(NT, 2)
k_mma(const float* __restrict__ bias, const float* __restrict__ Avec,
      const float* __restrict__ Zorig, float* __restrict__ out) {
    extern __shared__ char smc[];
    const uint32_t smb = smem_u32(smc);
    constexpr int KBIG = (MODE == 0) ? DZv : DHv;
    constexpr int NCB  = KBIG / BKH;
    constexpr int NC   = (MODE == 0) ? NCB : NCB + DSv / BKH;
    const __half* gA = (MODE == 0) ? g_Zh  : g_Hh;
    const __half* gB = (MODE == 0) ? g_W1h : g_W2h;

    const int tid = threadIdx.x, lane = tid & 31, wid = tid >> 5;
    const int wm = wid & 1, wn = wid >> 1;           // 2x2 warps, 64x64 each
    const int bm = blockIdx.y * BM, bn = blockIdx.x * BN;

    // cp.async loader: thread -> (row residue, 16B chunk)
    const int lrow = tid >> 2;      // 0..31
    const int lc   = tid & 3;       // 0..3

    // ldmatrix lane constants
    const int ro  = lane & 7;
    const int rA0 = ro + ((lane >> 3) & 1) * 8;   // A: sel&1 -> +8 rows
    const int cA  = lane >> 4;                    // A: sel>>1 -> +1 chunk
    const int rB0 = ro + ((lane >> 4) & 1) * 8;   // B: sel>>1 -> +8 rows
    const int cB  = (lane >> 3) & 1;              // B: sel&1 -> +1 chunk

    float acc[4][8][4];
#pragma unroll
    for (int i = 0; i < 4; i++)
#pragma unroll
        for (int j = 0; j < 8; j++)
#pragma unroll
            for (int k = 0; k < 4; k++) acc[i][j][k] = 0.f;

    auto issue = [&](int cn, int stg) {
        const __half *pa, *pb; int ld, ko;
        if (MODE == 1 && cn >= NCB) { pa = g_Sh; pb = g_Ch; ld = DSv; ko = (cn - NCB) * BKH; }
        else                        { pa = gA;   pb = gB;   ld = KBIG; ko = cn * BKH; }
        uint32_t sA = smb + stg * STAGEB;
        uint32_t sB = sA + TILEB;
#pragma unroll
        for (int i = 0; i < 4; i++) {
            int row = lrow + 32 * i;
            uint32_t so = row * 64 + ((lc ^ ((row >> 1) & 3)) << 4);
            cp16(sA + so, pa + (size_t)(bm + row) * ld + ko + lc * 8);
            cp16(sB + so, pb + (size_t)(bn + row) * ld + ko + lc * 8);
        }
    };

    auto comp = [&](int stg) {
        uint32_t sA = smb + stg * STAGEB;
        uint32_t sB = sA + TILEB;
#pragma unroll
        for (int ks = 0; ks < 2; ks++) {
            uint32_t af[4][4];
#pragma unroll
            for (int mt = 0; mt < 4; mt++) {
                int r = wm * 64 + mt * 16 + rA0;
                int c = ks * 2 + cA;
                ldsm4(af[mt], sA + r * 64 + ((c ^ ((r >> 1) & 3)) << 4));
            }
            uint32_t bf[8][2];
#pragma unroll
            for (int np = 0; np < 4; np++) {
                int r = wn * 64 + np * 16 + rB0;
                int c = ks * 2 + cB;
                uint32_t t[4];
                ldsm4(t, sB + r * 64 + ((c ^ ((r >> 1) & 3)) << 4));
                bf[2 * np][0] = t[0]; bf[2 * np][1] = t[1];
                bf[2 * np + 1][0] = t[2]; bf[2 * np + 1][1] = t[3];
            }
#pragma unroll
            for (int mt = 0; mt < 4; mt++)
#pragma unroll
                for (int nt = 0; nt < 8; nt++)
                    mma16(acc[mt][nt], af[mt], bf[nt][0], bf[nt][1]);
        }
    };

    // ---- 3-stage cp.async pipeline ----
    issue(0, 0); CP_COMMIT();
    issue(1, 1); CP_COMMIT();
#pragma unroll 1
    for (int c = 0; c < NC; c++) {
        if (c + 1 < NC) { CP_WAIT(1); } else { CP_WAIT(0); }
        __syncthreads();
        if (c + 2 < NC) { issue(c + 2, (c + 2) % 3); CP_COMMIT(); }
        comp(c % 3);
    }

    // ---- epilogue ----
    const int r0 = lane >> 2, cp2 = (lane & 3) * 2;
#pragma unroll
    for (int mt = 0; mt < 4; mt++) {
        const int row = bm + wm * 64 + mt * 16 + r0;
#pragma unroll
        for (int nt = 0; nt < 8; nt++) {
            const int col = bn + wn * 64 + nt * 8 + cp2;
            const float b0 = __ldg(bias + col), b1 = __ldg(bias + col + 1);
            if (MODE == 0) {
                __half2 v0 = __floats2half2_rn(fmaxf(acc[mt][nt][0] + b0, 0.f),
                                               fmaxf(acc[mt][nt][1] + b1, 0.f));
                __half2 v1 = __floats2half2_rn(fmaxf(acc[mt][nt][2] + b0, 0.f),
                                               fmaxf(acc[mt][nt][3] + b1, 0.f));
                *reinterpret_cast<__half2*>(g_Hh + (size_t)row * DHv + col) = v0;
                *reinterpret_cast<__half2*>(g_Hh + (size_t)(row + 8) * DHv + col) = v1;
            } else {
                const float a0 = __ldg(Avec + col), a1 = __ldg(Avec + col + 1);
                float2 z0 = *reinterpret_cast<const float2*>(Zorig + (size_t)row * DZv + col);
                float2 z1 = *reinterpret_cast<const float2*>(Zorig + (size_t)(row + 8) * DZv + col);
                float2 v0 = make_float2(acc[mt][nt][0] + a0 * z0.x + b0,
                                        acc[mt][nt][1] + a1 * z0.y + b1);
                float2 v1 = make_float2(acc[mt][nt][2] + a0 * z1.x + b0,
                                        acc[mt][nt][3] + a1 * z1.y + b1);
                *reinterpret_cast<float2*>(out + (size_t)row * DZv + col) = v0;
                *reinterpret_cast<float2*>(out + (size_t)(row + 8) * DZv + col) = v1;
            }
        }
    }
}

extern "C" void kernel_launch(void* const* d_in, const int* in_sizes, int n_in,
                              void* d_out, int out_size) {
    // metadata order: z, s, A, W1, W2, h1, h2, C
    const float* z  = (const float*)d_in[0];
    const float* s  = (const float*)d_in[1];
    const float* A  = (const float*)d_in[2];
    const float* W1 = (const float*)d_in[3];
    const float* W2 = (const float*)d_in[4];
    const float* h1 = (const float*)d_in[5];
    const float* h2 = (const float*)d_in[6];
    const float* C  = (const float*)d_in[7];
    float* out = (float*)d_out;
    (void)in_sizes; (void)n_in; (void)out_size;

    cudaFuncSetAttribute(k_mma<0>, cudaFuncAttributeMaxDynamicSharedMemorySize, SMEM_SZ);
    cudaFuncSetAttribute(k_mma<1>, cudaFuncAttributeMaxDynamicSharedMemorySize, SMEM_SZ);

    k_prep<<<dim3(1024, 5), 256>>>(z, W1, W2, s, C);
    k_mma<0><<<dim3(DHv / BN, DB / BM), NT, SMEM_SZ>>>(h1, nullptr, nullptr, nullptr);
    k_mma<1><<<dim3(DZv / BN, DB / BM), NT, SMEM_SZ>>>(h2, A, z, out);
}

// round 5
// speedup vs baseline: 8.5455x; 1.0098x over previous
#include <cuda_runtime.h>
#include <cuda_fp16.h>
#include <cstdint>

// PLRNN step via mma.sync fp16 (m16n8k16, fp32 accum), cp.async 3-stage pipeline,
// K-chunk 64, SW128 swizzle, fragment double-buffering.
//   prepass: convert Z,W1,W2,S,C to fp16
//   GEMM1:   H  = relu(Zh @ W1h^T + h1) -> fp16              [8192,4096]
//   GEMM2:   out = A*z + Hh @ W2h^T + h2 + Sh @ Ch^T         [8192,1024] fp32

#define NT 128
#define BM 128
#define BN 128
#define BKH 64            // K halves per chunk (128 B per row)
#define DB 8192
#define DZv 1024
#define DHv 4096
#define DSv 64

static __device__ __align__(256) __half g_Hh [(size_t)DB * DHv];
static __device__ __align__(256) __half g_Zh [(size_t)DB * DZv];
static __device__ __align__(256) __half g_W1h[(size_t)DHv * DZv];
static __device__ __align__(256) __half g_W2h[(size_t)DZv * DHv];
static __device__ __align__(256) __half g_Sh [(size_t)DB * DSv];
static __device__ __align__(256) __half g_Ch [(size_t)DZv * DSv];

#define TILEB  16384              // 128 rows x 128 B
#define STAGEB (2 * TILEB)
#define SMEM_SZ (3 * STAGEB)      // 98304

__device__ __forceinline__ uint32_t smem_u32(const void* p) {
    uint32_t a;
    asm("{ .reg .u64 t; cvta.to.shared.u64 t, %1; cvt.u32.u64 %0, t; }" : "=r"(a) : "l"(p));
    return a;
}
__device__ __forceinline__ void cp16(uint32_t s, const void* g) {
    asm volatile("cp.async.cg.shared.global [%0], [%1], 16;" :: "r"(s), "l"(g));
}
#define CP_COMMIT() asm volatile("cp.async.commit_group;" ::: "memory")
#define CP_WAIT(n)  asm volatile("cp.async.wait_group %0;" :: "n"(n) : "memory")

__device__ __forceinline__ void ldsm4(uint32_t (&r)[4], uint32_t a) {
    asm volatile("ldmatrix.sync.aligned.m8n8.x4.shared.b16 {%0,%1,%2,%3}, [%4];"
        : "=r"(r[0]), "=r"(r[1]), "=r"(r[2]), "=r"(r[3]) : "r"(a));
}
__device__ __forceinline__ void mma16(float (&d)[4], const uint32_t (&a)[4],
                                      uint32_t b0, uint32_t b1) {
    asm volatile("mma.sync.aligned.m16n8k16.row.col.f32.f16.f16.f32 "
        "{%0,%1,%2,%3}, {%4,%5,%6,%7}, {%8,%9}, {%0,%1,%2,%3};"
        : "+f"(d[0]), "+f"(d[1]), "+f"(d[2]), "+f"(d[3])
        : "r"(a[0]), "r"(a[1]), "r"(a[2]), "r"(a[3]), "r"(b0), "r"(b1));
}

// ---------------- prepass: fp32 -> fp16 ----------------
__global__ void k_prep(const float* __restrict__ z, const float* __restrict__ w1,
                       const float* __restrict__ w2, const float* __restrict__ s,
                       const float* __restrict__ c) {
    const float* src; __half* dst; size_t n8;
    switch (blockIdx.y) {
        case 0:  src = z;  dst = g_Zh;  n8 = (size_t)DB * DZv / 8;  break;
        case 1:  src = w1; dst = g_W1h; n8 = (size_t)DHv * DZv / 8; break;
        case 2:  src = w2; dst = g_W2h; n8 = (size_t)DZv * DHv / 8; break;
        case 3:  src = s;  dst = g_Sh;  n8 = (size_t)DB * DSv / 8;  break;
        default: src = c;  dst = g_Ch;  n8 = (size_t)DZv * DSv / 8; break;
    }
    size_t stride = (size_t)gridDim.x * blockDim.x;
    for (size_t i = (size_t)blockIdx.x * blockDim.x + threadIdx.x; i < n8; i += stride) {
        float4 v0 = reinterpret_cast<const float4*>(src)[2 * i];
        float4 v1 = reinterpret_cast<const float4*>(src)[2 * i + 1];
        __half2 h0 = __floats2half2_rn(v0.x, v0.y);
        __half2 h1 = __floats2half2_rn(v0.z, v0.w);
        __half2 h2 = __floats2half2_rn(v1.x, v1.y);
        __half2 h3 = __floats2half2_rn(v1.z, v1.w);
        uint4 o;
        o.x = *reinterpret_cast<uint32_t*>(&h0);
        o.y = *reinterpret_cast<uint32_t*>(&h1);
        o.z = *reinterpret_cast<uint32_t*>(&h2);
        o.w = *reinterpret_cast<uint32_t*>(&h3);
        reinterpret_cast<uint4*>(dst)[i] = o;
    }
}

// ---------------- fp16 mma GEMM (MODE 0: GEMM1, MODE 1: GEMM2) ----------------
template <int MODE>
__global__ void __launch_bounds__(NT, 2)
k_mma(const float* __restrict__ bias, const float* __restrict__ Avec,
      const float* __restrict__ Zorig, float* __restrict__ out) {
    extern __shared__ char smc[];
    const uint32_t smb = smem_u32(smc);
    constexpr int KBIG = (MODE == 0) ? DZv : DHv;
    constexpr int NCB  = KBIG / BKH;
    constexpr int NC   = (MODE == 0) ? NCB : NCB + 1;   // GEMM2: +1 chunk = S@C^T (K=64)
    const __half* gA = (MODE == 0) ? g_Zh  : g_Hh;
    const __half* gB = (MODE == 0) ? g_W1h : g_W2h;

    const int tid = threadIdx.x, lane = tid & 31, wid = tid >> 5;
    const int wm = wid & 1, wn = wid >> 1;           // 2x2 warps, 64x64 each
    const int bm = blockIdx.y * BM, bn = blockIdx.x * BN;

    // cp.async loader: thread -> (row residue 0..15, 16B chunk 0..7)
    const int lrow = tid >> 3;
    const int lc   = tid & 7;

    // ldmatrix lane constants
    const int rA  = lane & 15;                    // A row within 16-row frag
    const int cA  = lane >> 4;                    // A 16B-chunk within k16
    const int rB  = (lane & 7) + ((lane >> 4) & 1) * 8;
    const int cB  = (lane >> 3) & 1;

    float acc[4][8][4];
#pragma unroll
    for (int i = 0; i < 4; i++)
#pragma unroll
        for (int j = 0; j < 8; j++)
#pragma unroll
            for (int k = 0; k < 4; k++) acc[i][j][k] = 0.f;

    auto issue = [&](int cn, int stg) {
        const __half *pa, *pb; int ld, ko;
        if (MODE == 1 && cn >= NCB) { pa = g_Sh; pb = g_Ch; ld = DSv; ko = 0; }
        else                        { pa = gA;   pb = gB;   ld = KBIG; ko = cn * BKH; }
        uint32_t sA = smb + stg * STAGEB;
        uint32_t sB = sA + TILEB;
#pragma unroll
        for (int i = 0; i < 8; i++) {
            int row = lrow + 16 * i;
            uint32_t so = row * 128 + ((lc ^ (row & 7)) << 4);
            cp16(sA + so, pa + (size_t)(bm + row) * ld + ko + lc * 8);
            cp16(sB + so, pb + (size_t)(bn + row) * ld + ko + lc * 8);
        }
    };

    auto ldfrag = [&](int stg, int ks, uint32_t (&af)[4][4], uint32_t (&bf)[8][2]) {
        uint32_t sA = smb + stg * STAGEB;
        uint32_t sB = sA + TILEB;
#pragma unroll
        for (int mt = 0; mt < 4; mt++) {
            int r = wm * 64 + mt * 16 + rA;
            int c = 2 * ks + cA;
            ldsm4(af[mt], sA + r * 128 + ((c ^ (r & 7)) << 4));
        }
#pragma unroll
        for (int np = 0; np < 4; np++) {
            int r = wn * 64 + np * 16 + rB;
            int c = 2 * ks + cB;
            uint32_t t[4];
            ldsm4(t, sB + r * 128 + ((c ^ (r & 7)) << 4));
            bf[2 * np][0] = t[0];     bf[2 * np][1] = t[1];
            bf[2 * np + 1][0] = t[2]; bf[2 * np + 1][1] = t[3];
        }
    };

    // ---- 3-stage cp.async pipeline ----
    issue(0, 0); CP_COMMIT();
    issue(1, 1); CP_COMMIT();
#pragma unroll 1
    for (int c = 0; c < NC; c++) {
        if (c + 1 < NC) { CP_WAIT(1); } else { CP_WAIT(0); }
        __syncthreads();
        if (c + 2 < NC) { issue(c + 2, (c + 2) % 3); CP_COMMIT(); }

        const int stg = c % 3;
        uint32_t af[2][4][4], bf[2][8][2];
        ldfrag(stg, 0, af[0], bf[0]);
#pragma unroll
        for (int ks = 0; ks < 4; ks++) {
            if (ks < 3) ldfrag(stg, ks + 1, af[(ks + 1) & 1], bf[(ks + 1) & 1]);
            const int cur = ks & 1;
#pragma unroll
            for (int mt = 0; mt < 4; mt++)
#pragma unroll
                for (int nt = 0; nt < 8; nt++)
                    mma16(acc[mt][nt], af[cur][mt], bf[cur][nt][0], bf[cur][nt][1]);
        }
    }

    // ---- epilogue ----
    const int r0 = lane >> 2, cp2 = (lane & 3) * 2;
#pragma unroll
    for (int mt = 0; mt < 4; mt++) {
        const int row = bm + wm * 64 + mt * 16 + r0;
#pragma unroll
        for (int nt = 0; nt < 8; nt++) {
            const int col = bn + wn * 64 + nt * 8 + cp2;
            const float b0 = __ldg(bias + col), b1 = __ldg(bias + col + 1);
            if (MODE == 0) {
                __half2 v0 = __floats2half2_rn(fmaxf(acc[mt][nt][0] + b0, 0.f),
                                               fmaxf(acc[mt][nt][1] + b1, 0.f));
                __half2 v1 = __floats2half2_rn(fmaxf(acc[mt][nt][2] + b0, 0.f),
                                               fmaxf(acc[mt][nt][3] + b1, 0.f));
                *reinterpret_cast<__half2*>(g_Hh + (size_t)row * DHv + col) = v0;
                *reinterpret_cast<__half2*>(g_Hh + (size_t)(row + 8) * DHv + col) = v1;
            } else {
                const float a0 = __ldg(Avec + col), a1 = __ldg(Avec + col + 1);
                float2 z0 = *reinterpret_cast<const float2*>(Zorig + (size_t)row * DZv + col);
                float2 z1 = *reinterpret_cast<const float2*>(Zorig + (size_t)(row + 8) * DZv + col);
                float2 v0 = make_float2(acc[mt][nt][0] + a0 * z0.x + b0,
                                        acc[mt][nt][1] + a1 * z0.y + b1);
                float2 v1 = make_float2(acc[mt][nt][2] + a0 * z1.x + b0,
                                        acc[mt][nt][3] + a1 * z1.y + b1);
                *reinterpret_cast<float2*>(out + (size_t)row * DZv + col) = v0;
                *reinterpret_cast<float2*>(out + (size_t)(row + 8) * DZv + col) = v1;
            }
        }
    }
}

extern "C" void kernel_launch(void* const* d_in, const int* in_sizes, int n_in,
                              void* d_out, int out_size) {
    // metadata order: z, s, A, W1, W2, h1, h2, C
    const float* z  = (const float*)d_in[0];
    const float* s  = (const float*)d_in[1];
    const float* A  = (const float*)d_in[2];
    const float* W1 = (const float*)d_in[3];
    const float* W2 = (const float*)d_in[4];
    const float* h1 = (const float*)d_in[5];
    const float* h2 = (const float*)d_in[6];
    const float* C  = (const float*)d_in[7];
    float* out = (float*)d_out;
    (void)in_sizes; (void)n_in; (void)out_size;

    cudaFuncSetAttribute(k_mma<0>, cudaFuncAttributeMaxDynamicSharedMemorySize, SMEM_SZ);
    cudaFuncSetAttribute(k_mma<1>, cudaFuncAttributeMaxDynamicSharedMemorySize, SMEM_SZ);

    k_prep<<<dim3(1024, 5), 256>>>(z, W1, W2, s, C);
    k_mma<0><<<dim3(DHv / BN, DB / BM), NT, SMEM_SZ>>>(h1, nullptr, nullptr, nullptr);
    k_mma<1><<<dim3(DZv / BN, DB / BM), NT, SMEM_SZ>>>(h2, A, z, out);
}